// round 1
// baseline (speedup 1.0000x reference)
#include <cuda_runtime.h>
#include <cuda_bf16.h>
#include <math.h>

// Problem constants
static constexpr int B  = 4;
static constexpr int S  = 2048;
static constexpr int D  = 1024;
static constexpr int H  = 16;
static constexpr int DK = 64;
static constexpr int M  = B * S;      // 8192 rows for projection GEMMs

// Scratch buffers (allocation is forbidden; __device__ globals are the sanctioned path)
__device__ float g_Qp[B * S * D];
__device__ float g_Kp[B * S * D];
__device__ float g_Vp[B * S * D];
__device__ float g_X [B * S * D];

// ----------------------------------------------------------------------------
// SGEMM: C[m,n] = sum_k A[m,k] * W[n,k] + bias[n]
// A: [M,K] row-major, W: [N,K] row-major (torch Linear weight), C: [M,N]
// Tiles: 64x64x16, 256 threads, 4x4 micro-tile per thread.
// ----------------------------------------------------------------------------
#define GBM 64
#define GBN 64
#define GBK 16

__global__ __launch_bounds__(256)
void sgemm_bt_kernel(const float* __restrict__ A,
                     const float* __restrict__ W,
                     const float* __restrict__ bias,
                     float* __restrict__ C,
                     int Mdim, int Ndim, int Kdim)
{
    __shared__ float As[GBM][GBK + 1];
    __shared__ float Ws[GBN][GBK + 1];

    const int tx = threadIdx.x % 16;
    const int ty = threadIdx.x / 16;
    const int m0 = blockIdx.y * GBM;
    const int n0 = blockIdx.x * GBN;

    float acc[4][4] = {};

    for (int k0 = 0; k0 < Kdim; k0 += GBK) {
        // Cooperative load: 64x16 each for A and W
        #pragma unroll
        for (int i = threadIdx.x; i < GBM * GBK; i += 256) {
            int r = i / GBK;
            int c = i % GBK;
            As[r][c] = A[(size_t)(m0 + r) * Kdim + k0 + c];
            Ws[r][c] = W[(size_t)(n0 + r) * Kdim + k0 + c];
        }
        __syncthreads();

        #pragma unroll
        for (int kk = 0; kk < GBK; kk++) {
            float a[4], bb[4];
            #pragma unroll
            for (int i = 0; i < 4; i++) a[i]  = As[ty * 4 + i][kk];
            #pragma unroll
            for (int j = 0; j < 4; j++) bb[j] = Ws[tx * 4 + j][kk];
            #pragma unroll
            for (int i = 0; i < 4; i++)
                #pragma unroll
                for (int j = 0; j < 4; j++)
                    acc[i][j] = fmaf(a[i], bb[j], acc[i][j]);
        }
        __syncthreads();
    }

    #pragma unroll
    for (int i = 0; i < 4; i++) {
        int row = m0 + ty * 4 + i;
        #pragma unroll
        for (int j = 0; j < 4; j++) {
            int col = n0 + tx * 4 + j;
            C[(size_t)row * Ndim + col] = acc[i][j] + bias[col];
        }
    }
}

// ----------------------------------------------------------------------------
// Flash attention (fp32, online softmax).
// Grid: (S/128, H, B). Block: 128 threads, one query row per thread.
// Per key-tile of 64 rows: K/V tiles in shared (broadcast reads),
// per-thread scores staged in padded shared row.
// Dynamic smem: Ks 64*64 + Vs 64*64 + Ss 128*65 floats = 66048 bytes.
// ----------------------------------------------------------------------------
#define AT_BM 128
#define AT_BN 64

__global__ __launch_bounds__(128)
void attn_kernel(const float* __restrict__ Qp,
                 const float* __restrict__ Kp,
                 const float* __restrict__ Vp,
                 float* __restrict__ X)
{
    extern __shared__ float smem[];
    float* Ks = smem;                       // [64][64]
    float* Vs = smem + AT_BN * DK;          // [64][64]
    float* Ss = smem + 2 * AT_BN * DK;      // [128][65]

    const int b   = blockIdx.z;
    const int h   = blockIdx.y;
    const int q0  = blockIdx.x * AT_BM;
    const int tid = threadIdx.x;
    const int row = q0 + tid;

    const float scale = 0.125f;  // 1/sqrt(64)

    // q row into registers
    float qreg[DK];
    const float* qptr = Qp + ((size_t)(b * S + row)) * D + h * DK;
    #pragma unroll
    for (int d = 0; d < DK; d++) qreg[d] = qptr[d];

    float acc[DK];
    #pragma unroll
    for (int d = 0; d < DK; d++) acc[d] = 0.0f;
    float mval = -1e30f;
    float lval = 0.0f;

    float* myS = Ss + tid * (AT_BN + 1);

    for (int k0 = 0; k0 < S; k0 += AT_BN) {
        // Load K and V tiles (float4 vectorized, fully coalesced)
        const size_t kvbase = ((size_t)(b * S + k0)) * D + h * DK;
        #pragma unroll
        for (int i = tid; i < AT_BN * (DK / 4); i += AT_BM) {
            int r  = i / (DK / 4);
            int c4 = i % (DK / 4);
            float4 kv = *(const float4*)(Kp + kvbase + (size_t)r * D + c4 * 4);
            float4 vv = *(const float4*)(Vp + kvbase + (size_t)r * D + c4 * 4);
            *(float4*)(Ks + r * DK + c4 * 4) = kv;
            *(float4*)(Vs + r * DK + c4 * 4) = vv;
        }
        __syncthreads();

        // Scores for this thread's row vs the 64 keys (shared reads broadcast)
        float tmax = -1e30f;
        #pragma unroll 4
        for (int j = 0; j < AT_BN; j++) {
            const float4* kr = (const float4*)(Ks + j * DK);
            float s = 0.0f;
            #pragma unroll
            for (int d4 = 0; d4 < DK / 4; d4++) {
                float4 kv = kr[d4];
                s = fmaf(qreg[d4 * 4 + 0], kv.x, s);
                s = fmaf(qreg[d4 * 4 + 1], kv.y, s);
                s = fmaf(qreg[d4 * 4 + 2], kv.z, s);
                s = fmaf(qreg[d4 * 4 + 3], kv.w, s);
            }
            s *= scale;
            myS[j] = s;
            tmax = fmaxf(tmax, s);
        }

        // Online softmax update
        float mnew = fmaxf(mval, tmax);
        float corr = __expf(mval - mnew);
        lval *= corr;
        #pragma unroll
        for (int d = 0; d < DK; d++) acc[d] *= corr;

        #pragma unroll 2
        for (int j = 0; j < AT_BN; j++) {
            float p = __expf(myS[j] - mnew);
            lval += p;
            const float4* vr = (const float4*)(Vs + j * DK);
            #pragma unroll
            for (int d4 = 0; d4 < DK / 4; d4++) {
                float4 vv = vr[d4];
                acc[d4 * 4 + 0] = fmaf(p, vv.x, acc[d4 * 4 + 0]);
                acc[d4 * 4 + 1] = fmaf(p, vv.y, acc[d4 * 4 + 1]);
                acc[d4 * 4 + 2] = fmaf(p, vv.z, acc[d4 * 4 + 2]);
                acc[d4 * 4 + 3] = fmaf(p, vv.w, acc[d4 * 4 + 3]);
            }
        }
        mval = mnew;
        __syncthreads();
    }

    const float inv = 1.0f / lval;
    float* xp = g_X + ((size_t)(b * S + row)) * D + h * DK;
    #pragma unroll
    for (int d = 0; d < DK; d++) xp[d] = acc[d] * inv;
}

// ----------------------------------------------------------------------------
// Launch
// ----------------------------------------------------------------------------
extern "C" void kernel_launch(void* const* d_in, const int* in_sizes, int n_in,
                              void* d_out, int out_size)
{
    const float* q  = (const float*)d_in[0];
    const float* k  = (const float*)d_in[1];
    const float* v  = (const float*)d_in[2];
    const float* Wq = (const float*)d_in[3];
    const float* bq = (const float*)d_in[4];
    const float* Wk = (const float*)d_in[5];
    const float* bk = (const float*)d_in[6];
    const float* Wv = (const float*)d_in[7];
    const float* bv = (const float*)d_in[8];
    const float* Wo = (const float*)d_in[9];
    const float* bo = (const float*)d_in[10];
    float* out = (float*)d_out;

    float *Qp, *Kp, *Vp, *X;
    cudaGetSymbolAddress((void**)&Qp, g_Qp);
    cudaGetSymbolAddress((void**)&Kp, g_Kp);
    cudaGetSymbolAddress((void**)&Vp, g_Vp);
    cudaGetSymbolAddress((void**)&X,  g_X);

    // Projections: [8192,1024] x [1024,1024]^T
    dim3 gemmGrid(D / GBN, M / GBM);
    sgemm_bt_kernel<<<gemmGrid, 256>>>(q, Wq, bq, Qp, M, D, D);
    sgemm_bt_kernel<<<gemmGrid, 256>>>(k, Wk, bk, Kp, M, D, D);
    sgemm_bt_kernel<<<gemmGrid, 256>>>(v, Wv, bv, Vp, M, D, D);

    // Flash attention
    static const int attn_smem = (2 * AT_BN * DK + AT_BM * (AT_BN + 1)) * (int)sizeof(float);
    cudaFuncSetAttribute(attn_kernel, cudaFuncAttributeMaxDynamicSharedMemorySize, attn_smem);
    dim3 attnGrid(S / AT_BM, H, B);
    attn_kernel<<<attnGrid, AT_BM, attn_smem>>>(Qp, Kp, Vp, X);

    // Output projection
    sgemm_bt_kernel<<<gemmGrid, 256>>>(X, Wo, bo, out, M, D, D);
}

// round 4
// speedup vs baseline: 1.4904x; 1.4904x over previous
#include <cuda_runtime.h>
#include <cuda_bf16.h>
#include <cstdint>
#include <math.h>

// Problem constants
static constexpr int B  = 4;
static constexpr int S  = 2048;
static constexpr int D  = 1024;
static constexpr int H  = 16;
static constexpr int DK = 64;
static constexpr int M  = B * S;      // 8192
static constexpr int K3 = 3 * D;      // 3072: bf16x3 concatenated K

// Scratch (__device__ globals; allocation forbidden)
__device__ float g_Qp[B * S * D];
__device__ float g_Kp[B * S * D];
__device__ float g_Vp[B * S * D];
__device__ float g_X [B * S * D];
__device__ __nv_bfloat16 g_Abig[(size_t)M * K3];   // 48 MB
__device__ __nv_bfloat16 g_Wbig[(size_t)D * K3];   // 6 MB

__device__ __forceinline__ uint32_t smem_u32(const void* p) {
    uint32_t a;
    asm("{ .reg .u64 t; cvta.to.shared.u64 t, %1; cvt.u32.u64 %0, t; }" : "=r"(a) : "l"(p));
    return a;
}

// ============================================================================
// bf16x3 splits.
// Activations: [rows][1024] fp32 -> [rows][3072] bf16 = [hi | hi | lo]
// Weights:     [rows][1024] fp32 -> [rows][3072] bf16 = [hi | lo | hi]
// Dot(A_row, W_row) = Ah.Wh + Ah.Wl + Al.Wh  (drops only Al.Wl ~ eps^2)
// ============================================================================
__global__ __launch_bounds__(256)
void split3_a_kernel(const float* __restrict__ src, __nv_bfloat16* __restrict__ dst)
{
    const int r = blockIdx.x;
    const int c = threadIdx.x * 4;
    float4 x = *(const float4*)(src + (size_t)r * D + c);

    __align__(8) __nv_bfloat16 h[4];
    __align__(8) __nv_bfloat16 l[4];
    float xs[4] = {x.x, x.y, x.z, x.w};
    #pragma unroll
    for (int i = 0; i < 4; i++) {
        h[i] = __float2bfloat16(xs[i]);
        l[i] = __float2bfloat16(xs[i] - __bfloat162float(h[i]));
    }
    __nv_bfloat16* drow = dst + (size_t)r * K3;
    *(uint2*)(drow + c)         = *(uint2*)h;   // hi
    *(uint2*)(drow + D + c)     = *(uint2*)h;   // hi
    *(uint2*)(drow + 2 * D + c) = *(uint2*)l;   // lo
}

__global__ __launch_bounds__(256)
void split3_w_kernel(const float* __restrict__ src, __nv_bfloat16* __restrict__ dst)
{
    const int r = blockIdx.x;
    const int c = threadIdx.x * 4;
    float4 x = *(const float4*)(src + (size_t)r * D + c);

    __align__(8) __nv_bfloat16 h[4];
    __align__(8) __nv_bfloat16 l[4];
    float xs[4] = {x.x, x.y, x.z, x.w};
    #pragma unroll
    for (int i = 0; i < 4; i++) {
        h[i] = __float2bfloat16(xs[i]);
        l[i] = __float2bfloat16(xs[i] - __bfloat162float(h[i]));
    }
    __nv_bfloat16* drow = dst + (size_t)r * K3;
    *(uint2*)(drow + c)         = *(uint2*)h;   // hi
    *(uint2*)(drow + D + c)     = *(uint2*)l;   // lo
    *(uint2*)(drow + 2 * D + c) = *(uint2*)h;   // hi
}

// ============================================================================
// Tensor-core GEMM via mma.sync (HMMA): C[m,n] = sum_k A[m,k]*Wt[n,k] + bias[n]
// A: [M][Kdim] bf16, Wt: [1024][Kdim] bf16, C: [M][1024] fp32.
// Block 128x128, BK=32, 256 threads (2x4 warps, 64x32 warp tile).
// 4-stage cp.async pipeline; smem rows padded to 40 bf16 (80B) -> conflict-free
// ldmatrix (8 rows x 16B footprint covers all 32 banks exactly once).
// ============================================================================
static constexpr int BKG     = 32;
static constexpr int PADK    = 40;                   // padded row, bf16 elems
static constexpr int TILE_B  = 128 * PADK * 2;       // 10240 bytes (A or B tile)
static constexpr int STAGE_B = 2 * TILE_B;           // 20480
static constexpr int NSTAGE  = 4;
static constexpr int GEMM_SMEM = NSTAGE * STAGE_B;   // 81920

#define CP_ASYNC16(sm, gm) \
    asm volatile("cp.async.cg.shared.global [%0], [%1], 16;" :: "r"(sm), "l"(gm) : "memory")
#define CP_COMMIT() asm volatile("cp.async.commit_group;" ::: "memory")
#define CP_WAIT2()  asm volatile("cp.async.wait_group 2;" ::: "memory")

#define LDMATRIX_X4(r0, r1, r2, r3, addr) \
    asm volatile("ldmatrix.sync.aligned.m8n8.x4.shared.b16 {%0,%1,%2,%3}, [%4];" \
        : "=r"(r0), "=r"(r1), "=r"(r2), "=r"(r3) : "r"(addr))

#define MMA_BF16(d0, d1, d2, d3, a0, a1, a2, a3, b0, b1) \
    asm volatile("mma.sync.aligned.m16n8k16.row.col.f32.bf16.bf16.f32 " \
        "{%0,%1,%2,%3}, {%4,%5,%6,%7}, {%8,%9}, {%0,%1,%2,%3};" \
        : "+f"(d0), "+f"(d1), "+f"(d2), "+f"(d3) \
        : "r"(a0), "r"(a1), "r"(a2), "r"(a3), "r"(b0), "r"(b1))

__global__ __launch_bounds__(256)
void gemm_mma_kernel(const __nv_bfloat16* __restrict__ A,
                     const __nv_bfloat16* __restrict__ Wt,
                     const float* __restrict__ bias,
                     float* __restrict__ C,
                     int Kdim)
{
    extern __shared__ __align__(128) char smem[];
    const uint32_t sb = smem_u32(smem);

    const int tid  = threadIdx.x;
    const int wid  = tid >> 5;
    const int lane = tid & 31;
    const int wm   = wid >> 2;          // 0..1  (M dir, 64 rows each)
    const int wn   = wid & 3;           // 0..3  (N dir, 32 cols each)
    const int g    = lane >> 2;         // group 0..7
    const int tg   = lane & 3;          // thread-in-group

    const int m0 = blockIdx.y * 128;
    const int n0 = blockIdx.x * 128;
    const int NK = Kdim / BKG;          // 96

    const int r0c = tid >> 2,         s0c = tid & 3;
    const int r1c = (tid + 256) >> 2, s1c = (tid + 256) & 3;

    auto issue_stage = [&](int stage, int kt) {
        const uint32_t sa  = sb + stage * STAGE_B;
        const uint32_t sbf = sa + TILE_B;
        const __nv_bfloat16* gA = A  + (size_t)(m0) * Kdim + kt * BKG;
        const __nv_bfloat16* gB = Wt + (size_t)(n0) * Kdim + kt * BKG;
        CP_ASYNC16(sa  + r0c * (PADK * 2) + s0c * 16, gA + (size_t)r0c * Kdim + s0c * 8);
        CP_ASYNC16(sa  + r1c * (PADK * 2) + s1c * 16, gA + (size_t)r1c * Kdim + s1c * 8);
        CP_ASYNC16(sbf + r0c * (PADK * 2) + s0c * 16, gB + (size_t)r0c * Kdim + s0c * 8);
        CP_ASYNC16(sbf + r1c * (PADK * 2) + s1c * 16, gB + (size_t)r1c * Kdim + s1c * 8);
        CP_COMMIT();
    };

    const int a_row = (lane & 7) + ((lane >> 3) & 1) * 8;
    const int a_k8  = ((lane >> 4) & 1) * 8;
    const int b_row = (lane & 7) + ((lane >> 4) & 1) * 8;
    const int b_k8  = ((lane >> 3) & 1) * 8;

    float acc[4][4][4];
    #pragma unroll
    for (int i = 0; i < 4; i++)
        #pragma unroll
        for (int j = 0; j < 4; j++)
            #pragma unroll
            for (int e = 0; e < 4; e++) acc[i][j][e] = 0.0f;

    issue_stage(0, 0);
    issue_stage(1, 1);
    issue_stage(2, 2);

    for (int kt = 0; kt < NK; kt++) {
        CP_WAIT2();
        __syncthreads();

        if (kt + 3 < NK) issue_stage((kt + 3) & 3, kt + 3);

        const uint32_t sa  = sb + ((kt & 3) * STAGE_B);
        const uint32_t sbf = sa + TILE_B;

        #pragma unroll
        for (int ks = 0; ks < 2; ks++) {
            const int kcol = ks * 16;
            uint32_t a[4][4];
            #pragma unroll
            for (int mt = 0; mt < 4; mt++) {
                uint32_t ad = sa + (uint32_t)(wm * 64 + mt * 16 + a_row) * (PADK * 2)
                                 + (uint32_t)(kcol + a_k8) * 2;
                LDMATRIX_X4(a[mt][0], a[mt][1], a[mt][2], a[mt][3], ad);
            }
            uint32_t bf[4][2];
            #pragma unroll
            for (int p = 0; p < 2; p++) {
                uint32_t bd = sbf + (uint32_t)(wn * 32 + p * 16 + b_row) * (PADK * 2)
                                  + (uint32_t)(kcol + b_k8) * 2;
                uint32_t x0, x1, x2, x3;
                LDMATRIX_X4(x0, x1, x2, x3, bd);
                bf[p * 2 + 0][0] = x0; bf[p * 2 + 0][1] = x1;
                bf[p * 2 + 1][0] = x2; bf[p * 2 + 1][1] = x3;
            }
            #pragma unroll
            for (int mt = 0; mt < 4; mt++)
                #pragma unroll
                for (int nt = 0; nt < 4; nt++)
                    MMA_BF16(acc[mt][nt][0], acc[mt][nt][1], acc[mt][nt][2], acc[mt][nt][3],
                             a[mt][0], a[mt][1], a[mt][2], a[mt][3],
                             bf[nt][0], bf[nt][1]);
        }
        __syncthreads();
    }

    #pragma unroll
    for (int mt = 0; mt < 4; mt++) {
        const int row = m0 + wm * 64 + mt * 16 + g;
        #pragma unroll
        for (int nt = 0; nt < 4; nt++) {
            const int col = n0 + wn * 32 + nt * 8 + tg * 2;
            const float b0 = bias[col], b1 = bias[col + 1];
            float2 v0 = make_float2(acc[mt][nt][0] + b0, acc[mt][nt][1] + b1);
            float2 v1 = make_float2(acc[mt][nt][2] + b0, acc[mt][nt][3] + b1);
            *(float2*)(C + (size_t)row * D + col)       = v0;
            *(float2*)(C + (size_t)(row + 8) * D + col) = v1;
        }
    }
}

// ----------------------------------------------------------------------------
// Flash attention (fp32, online softmax) — unchanged (known correct)
// ----------------------------------------------------------------------------
#define AT_BM 128
#define AT_BN 64

__global__ __launch_bounds__(128)
void attn_kernel(const float* __restrict__ Qp,
                 const float* __restrict__ Kp,
                 const float* __restrict__ Vp,
                 float* __restrict__ X)
{
    extern __shared__ float asmem[];
    float* Ks = asmem;
    float* Vs = asmem + AT_BN * DK;
    float* Ss = asmem + 2 * AT_BN * DK;

    const int b   = blockIdx.z;
    const int h   = blockIdx.y;
    const int q0  = blockIdx.x * AT_BM;
    const int tid = threadIdx.x;
    const int row = q0 + tid;

    const float scale = 0.125f;

    float qreg[DK];
    const float* qptr = Qp + ((size_t)(b * S + row)) * D + h * DK;
    #pragma unroll
    for (int d = 0; d < DK; d++) qreg[d] = qptr[d];

    float acc[DK];
    #pragma unroll
    for (int d = 0; d < DK; d++) acc[d] = 0.0f;
    float mval = -1e30f;
    float lval = 0.0f;

    float* myS = Ss + tid * (AT_BN + 1);

    for (int k0 = 0; k0 < S; k0 += AT_BN) {
        const size_t kvbase = ((size_t)(b * S + k0)) * D + h * DK;
        #pragma unroll
        for (int i = tid; i < AT_BN * (DK / 4); i += AT_BM) {
            int r  = i / (DK / 4);
            int c4 = i % (DK / 4);
            float4 kv = *(const float4*)(Kp + kvbase + (size_t)r * D + c4 * 4);
            float4 vv = *(const float4*)(Vp + kvbase + (size_t)r * D + c4 * 4);
            *(float4*)(Ks + r * DK + c4 * 4) = kv;
            *(float4*)(Vs + r * DK + c4 * 4) = vv;
        }
        __syncthreads();

        float tmax = -1e30f;
        #pragma unroll 4
        for (int j = 0; j < AT_BN; j++) {
            const float4* kr = (const float4*)(Ks + j * DK);
            float s = 0.0f;
            #pragma unroll
            for (int d4 = 0; d4 < DK / 4; d4++) {
                float4 kv = kr[d4];
                s = fmaf(qreg[d4 * 4 + 0], kv.x, s);
                s = fmaf(qreg[d4 * 4 + 1], kv.y, s);
                s = fmaf(qreg[d4 * 4 + 2], kv.z, s);
                s = fmaf(qreg[d4 * 4 + 3], kv.w, s);
            }
            s *= scale;
            myS[j] = s;
            tmax = fmaxf(tmax, s);
        }

        float mnew = fmaxf(mval, tmax);
        float corr = __expf(mval - mnew);
        lval *= corr;
        #pragma unroll
        for (int d = 0; d < DK; d++) acc[d] *= corr;

        #pragma unroll 2
        for (int j = 0; j < AT_BN; j++) {
            float p = __expf(myS[j] - mnew);
            lval += p;
            const float4* vr = (const float4*)(Vs + j * DK);
            #pragma unroll
            for (int d4 = 0; d4 < DK / 4; d4++) {
                float4 vv = vr[d4];
                acc[d4 * 4 + 0] = fmaf(p, vv.x, acc[d4 * 4 + 0]);
                acc[d4 * 4 + 1] = fmaf(p, vv.y, acc[d4 * 4 + 1]);
                acc[d4 * 4 + 2] = fmaf(p, vv.z, acc[d4 * 4 + 2]);
                acc[d4 * 4 + 3] = fmaf(p, vv.w, acc[d4 * 4 + 3]);
            }
        }
        mval = mnew;
        __syncthreads();
    }

    const float inv = 1.0f / lval;
    float* xp = X + ((size_t)(b * S + row)) * D + h * DK;
    #pragma unroll
    for (int d = 0; d < DK; d++) xp[d] = acc[d] * inv;
}

// ----------------------------------------------------------------------------
// Launch
// ----------------------------------------------------------------------------
extern "C" void kernel_launch(void* const* d_in, const int* in_sizes, int n_in,
                              void* d_out, int out_size)
{
    const float* q  = (const float*)d_in[0];
    const float* k  = (const float*)d_in[1];
    const float* v  = (const float*)d_in[2];
    const float* Wq = (const float*)d_in[3];
    const float* bq = (const float*)d_in[4];
    const float* Wk = (const float*)d_in[5];
    const float* bk = (const float*)d_in[6];
    const float* Wv = (const float*)d_in[7];
    const float* bv = (const float*)d_in[8];
    const float* Wo = (const float*)d_in[9];
    const float* bo = (const float*)d_in[10];
    float* out = (float*)d_out;

    float *Qp, *Kp, *Vp, *X;
    __nv_bfloat16 *Abig, *Wbig;
    cudaGetSymbolAddress((void**)&Qp,   g_Qp);
    cudaGetSymbolAddress((void**)&Kp,   g_Kp);
    cudaGetSymbolAddress((void**)&Vp,   g_Vp);
    cudaGetSymbolAddress((void**)&X,    g_X);
    cudaGetSymbolAddress((void**)&Abig, g_Abig);
    cudaGetSymbolAddress((void**)&Wbig, g_Wbig);

    cudaFuncSetAttribute(gemm_mma_kernel,
                         cudaFuncAttributeMaxDynamicSharedMemorySize, GEMM_SMEM);

    dim3 gemmGrid(D / 128, M / 128);   // (8, 64)

    // Q projection
    split3_w_kernel<<<D, 256>>>(Wq, Wbig);
    split3_a_kernel<<<M, 256>>>(q, Abig);
    gemm_mma_kernel<<<gemmGrid, 256, GEMM_SMEM>>>(Abig, Wbig, bq, Qp, K3);
    // K projection
    split3_w_kernel<<<D, 256>>>(Wk, Wbig);
    split3_a_kernel<<<M, 256>>>(k, Abig);
    gemm_mma_kernel<<<gemmGrid, 256, GEMM_SMEM>>>(Abig, Wbig, bk, Kp, K3);
    // V projection
    split3_w_kernel<<<D, 256>>>(Wv, Wbig);
    split3_a_kernel<<<M, 256>>>(v, Abig);
    gemm_mma_kernel<<<gemmGrid, 256, GEMM_SMEM>>>(Abig, Wbig, bv, Vp, K3);

    // Flash attention
    static const int attn_smem = (2 * AT_BN * DK + AT_BM * (AT_BN + 1)) * (int)sizeof(float);
    cudaFuncSetAttribute(attn_kernel, cudaFuncAttributeMaxDynamicSharedMemorySize, attn_smem);
    dim3 attnGrid(S / AT_BM, H, B);
    attn_kernel<<<attnGrid, AT_BM, attn_smem>>>(Qp, Kp, Vp, X);

    // Output projection
    split3_w_kernel<<<D, 256>>>(Wo, Wbig);
    split3_a_kernel<<<M, 256>>>(X, Abig);
    gemm_mma_kernel<<<gemmGrid, 256, GEMM_SMEM>>>(Abig, Wbig, bo, out, K3);
}

// round 5
// speedup vs baseline: 4.5822x; 3.0745x over previous
#include <cuda_runtime.h>
#include <cuda_bf16.h>
#include <cuda_fp16.h>
#include <cstdint>
#include <math.h>

// Problem constants
static constexpr int B  = 4;
static constexpr int S  = 2048;
static constexpr int D  = 1024;
static constexpr int H  = 16;
static constexpr int DK = 64;
static constexpr int M  = B * S;      // 8192
static constexpr int K3 = 3 * D;      // 3072: bf16x3 concatenated K

// Scratch (__device__ globals; allocation forbidden)
__device__ __half g_Qh[(size_t)M * D];             // 16 MB, fp16 projected Q
__device__ __half g_Kh[(size_t)M * D];             // 16 MB
__device__ __half g_Vh[(size_t)M * D];             // 16 MB
__device__ float  g_X [(size_t)M * D];             // 32 MB, attention output
__device__ __nv_bfloat16 g_Abig[(size_t)M * K3];   // 48 MB
__device__ __nv_bfloat16 g_Wbig[(size_t)D * K3];   // 6 MB

__device__ __forceinline__ uint32_t smem_u32(const void* p) {
    uint32_t a;
    asm("{ .reg .u64 t; cvta.to.shared.u64 t, %1; cvt.u32.u64 %0, t; }" : "=r"(a) : "l"(p));
    return a;
}

// ============================================================================
// bf16x3 splits (activation: [hi|hi|lo], weight: [hi|lo|hi])
// ============================================================================
__global__ __launch_bounds__(256)
void split3_a_kernel(const float* __restrict__ src, __nv_bfloat16* __restrict__ dst)
{
    const int r = blockIdx.x;
    const int c = threadIdx.x * 4;
    float4 x = *(const float4*)(src + (size_t)r * D + c);

    __align__(8) __nv_bfloat16 h[4];
    __align__(8) __nv_bfloat16 l[4];
    float xs[4] = {x.x, x.y, x.z, x.w};
    #pragma unroll
    for (int i = 0; i < 4; i++) {
        h[i] = __float2bfloat16(xs[i]);
        l[i] = __float2bfloat16(xs[i] - __bfloat162float(h[i]));
    }
    __nv_bfloat16* drow = dst + (size_t)r * K3;
    *(uint2*)(drow + c)         = *(uint2*)h;
    *(uint2*)(drow + D + c)     = *(uint2*)h;
    *(uint2*)(drow + 2 * D + c) = *(uint2*)l;
}

__global__ __launch_bounds__(256)
void split3_w_kernel(const float* __restrict__ src, __nv_bfloat16* __restrict__ dst)
{
    const int r = blockIdx.x;
    const int c = threadIdx.x * 4;
    float4 x = *(const float4*)(src + (size_t)r * D + c);

    __align__(8) __nv_bfloat16 h[4];
    __align__(8) __nv_bfloat16 l[4];
    float xs[4] = {x.x, x.y, x.z, x.w};
    #pragma unroll
    for (int i = 0; i < 4; i++) {
        h[i] = __float2bfloat16(xs[i]);
        l[i] = __float2bfloat16(xs[i] - __bfloat162float(h[i]));
    }
    __nv_bfloat16* drow = dst + (size_t)r * K3;
    *(uint2*)(drow + c)         = *(uint2*)h;
    *(uint2*)(drow + D + c)     = *(uint2*)l;
    *(uint2*)(drow + 2 * D + c) = *(uint2*)h;
}

// ============================================================================
// HMMA GEMM (bf16x3): C[m,n] = sum_k A[m,k]*Wt[n,k] + bias[n]
// OutT = float (fp32 out) or __half (fp16 out for attention inputs).
// ============================================================================
static constexpr int BKG     = 32;
static constexpr int PADK    = 40;
static constexpr int TILE_B  = 128 * PADK * 2;
static constexpr int STAGE_B = 2 * TILE_B;
static constexpr int NSTAGE  = 4;
static constexpr int GEMM_SMEM = NSTAGE * STAGE_B;   // 81920

#define CP_ASYNC16(sm, gm) \
    asm volatile("cp.async.cg.shared.global [%0], [%1], 16;" :: "r"(sm), "l"(gm) : "memory")
#define CP_COMMIT() asm volatile("cp.async.commit_group;" ::: "memory")
#define CP_WAIT2()  asm volatile("cp.async.wait_group 2;" ::: "memory")

#define LDMATRIX_X4(r0, r1, r2, r3, addr) \
    asm volatile("ldmatrix.sync.aligned.m8n8.x4.shared.b16 {%0,%1,%2,%3}, [%4];" \
        : "=r"(r0), "=r"(r1), "=r"(r2), "=r"(r3) : "r"(addr))

#define LDMATRIX_X4_T(r0, r1, r2, r3, addr) \
    asm volatile("ldmatrix.sync.aligned.m8n8.x4.trans.shared.b16 {%0,%1,%2,%3}, [%4];" \
        : "=r"(r0), "=r"(r1), "=r"(r2), "=r"(r3) : "r"(addr))

#define MMA_BF16(d0, d1, d2, d3, a0, a1, a2, a3, b0, b1) \
    asm volatile("mma.sync.aligned.m16n8k16.row.col.f32.bf16.bf16.f32 " \
        "{%0,%1,%2,%3}, {%4,%5,%6,%7}, {%8,%9}, {%0,%1,%2,%3};" \
        : "+f"(d0), "+f"(d1), "+f"(d2), "+f"(d3) \
        : "r"(a0), "r"(a1), "r"(a2), "r"(a3), "r"(b0), "r"(b1))

#define MMA_F16(d0, d1, d2, d3, a0, a1, a2, a3, b0, b1) \
    asm volatile("mma.sync.aligned.m16n8k16.row.col.f32.f16.f16.f32 " \
        "{%0,%1,%2,%3}, {%4,%5,%6,%7}, {%8,%9}, {%0,%1,%2,%3};" \
        : "+f"(d0), "+f"(d1), "+f"(d2), "+f"(d3) \
        : "r"(a0), "r"(a1), "r"(a2), "r"(a3), "r"(b0), "r"(b1))

template<typename OutT>
__global__ __launch_bounds__(256)
void gemm_mma_kernel(const __nv_bfloat16* __restrict__ A,
                     const __nv_bfloat16* __restrict__ Wt,
                     const float* __restrict__ bias,
                     OutT* __restrict__ C,
                     int Kdim)
{
    extern __shared__ __align__(128) char smem[];
    const uint32_t sb = smem_u32(smem);

    const int tid  = threadIdx.x;
    const int wid  = tid >> 5;
    const int lane = tid & 31;
    const int wm   = wid >> 2;
    const int wn   = wid & 3;
    const int g    = lane >> 2;
    const int tg   = lane & 3;

    const int m0 = blockIdx.y * 128;
    const int n0 = blockIdx.x * 128;
    const int NK = Kdim / BKG;

    const int r0c = tid >> 2,         s0c = tid & 3;
    const int r1c = (tid + 256) >> 2, s1c = (tid + 256) & 3;

    auto issue_stage = [&](int stage, int kt) {
        const uint32_t sa  = sb + stage * STAGE_B;
        const uint32_t sbf = sa + TILE_B;
        const __nv_bfloat16* gA = A  + (size_t)(m0) * Kdim + kt * BKG;
        const __nv_bfloat16* gB = Wt + (size_t)(n0) * Kdim + kt * BKG;
        CP_ASYNC16(sa  + r0c * (PADK * 2) + s0c * 16, gA + (size_t)r0c * Kdim + s0c * 8);
        CP_ASYNC16(sa  + r1c * (PADK * 2) + s1c * 16, gA + (size_t)r1c * Kdim + s1c * 8);
        CP_ASYNC16(sbf + r0c * (PADK * 2) + s0c * 16, gB + (size_t)r0c * Kdim + s0c * 8);
        CP_ASYNC16(sbf + r1c * (PADK * 2) + s1c * 16, gB + (size_t)r1c * Kdim + s1c * 8);
        CP_COMMIT();
    };

    const int a_row = (lane & 7) + ((lane >> 3) & 1) * 8;
    const int a_k8  = ((lane >> 4) & 1) * 8;
    const int b_row = (lane & 7) + ((lane >> 4) & 1) * 8;
    const int b_k8  = ((lane >> 3) & 1) * 8;

    float acc[4][4][4];
    #pragma unroll
    for (int i = 0; i < 4; i++)
        #pragma unroll
        for (int j = 0; j < 4; j++)
            #pragma unroll
            for (int e = 0; e < 4; e++) acc[i][j][e] = 0.0f;

    issue_stage(0, 0);
    issue_stage(1, 1);
    issue_stage(2, 2);

    for (int kt = 0; kt < NK; kt++) {
        CP_WAIT2();
        __syncthreads();

        if (kt + 3 < NK) issue_stage((kt + 3) & 3, kt + 3);

        const uint32_t sa  = sb + ((kt & 3) * STAGE_B);
        const uint32_t sbf = sa + TILE_B;

        #pragma unroll
        for (int ks = 0; ks < 2; ks++) {
            const int kcol = ks * 16;
            uint32_t a[4][4];
            #pragma unroll
            for (int mt = 0; mt < 4; mt++) {
                uint32_t ad = sa + (uint32_t)(wm * 64 + mt * 16 + a_row) * (PADK * 2)
                                 + (uint32_t)(kcol + a_k8) * 2;
                LDMATRIX_X4(a[mt][0], a[mt][1], a[mt][2], a[mt][3], ad);
            }
            uint32_t bf[4][2];
            #pragma unroll
            for (int p = 0; p < 2; p++) {
                uint32_t bd = sbf + (uint32_t)(wn * 32 + p * 16 + b_row) * (PADK * 2)
                                  + (uint32_t)(kcol + b_k8) * 2;
                uint32_t x0, x1, x2, x3;
                LDMATRIX_X4(x0, x1, x2, x3, bd);
                bf[p * 2 + 0][0] = x0; bf[p * 2 + 0][1] = x1;
                bf[p * 2 + 1][0] = x2; bf[p * 2 + 1][1] = x3;
            }
            #pragma unroll
            for (int mt = 0; mt < 4; mt++)
                #pragma unroll
                for (int nt = 0; nt < 4; nt++)
                    MMA_BF16(acc[mt][nt][0], acc[mt][nt][1], acc[mt][nt][2], acc[mt][nt][3],
                             a[mt][0], a[mt][1], a[mt][2], a[mt][3],
                             bf[nt][0], bf[nt][1]);
        }
        __syncthreads();
    }

    #pragma unroll
    for (int mt = 0; mt < 4; mt++) {
        const int row = m0 + wm * 64 + mt * 16 + g;
        #pragma unroll
        for (int nt = 0; nt < 4; nt++) {
            const int col = n0 + wn * 32 + nt * 8 + tg * 2;
            const float b0 = bias[col], b1 = bias[col + 1];
            float2 v0 = make_float2(acc[mt][nt][0] + b0, acc[mt][nt][1] + b1);
            float2 v1 = make_float2(acc[mt][nt][2] + b0, acc[mt][nt][3] + b1);
            if constexpr (sizeof(OutT) == 4) {
                *(float2*)((float*)C + (size_t)row * D + col)       = v0;
                *(float2*)((float*)C + (size_t)(row + 8) * D + col) = v1;
            } else {
                __half2 h0 = __floats2half2_rn(v0.x, v0.y);
                __half2 h1 = __floats2half2_rn(v1.x, v1.y);
                *(__half2*)((__half*)C + (size_t)row * D + col)       = h0;
                *(__half2*)((__half*)C + (size_t)(row + 8) * D + col) = h1;
            }
        }
    }
}

// ============================================================================
// fp16 HMMA flash attention (FA2 layout).
// Grid (S/128, H, B), 256 threads = 8 warps, 16 q-rows/warp.
// KV tiles of 64 keys; K/V smem [64][72] fp16, double-buffered cp.async.
// Smem: Q 128*72*2 = 18432 + 2 stages * 18432 = 55296 bytes.
// ============================================================================
static constexpr int AT_SMEM = 18432 * 3;
static constexpr int PAD64   = 72;     // 144B pitch = 9*16B -> conflict-free

__global__ __launch_bounds__(256)
void attn_mma_kernel(const __half* __restrict__ Q,
                     const __half* __restrict__ K,
                     const __half* __restrict__ V,
                     float* __restrict__ X)
{
    extern __shared__ __align__(128) char asmem[];
    const uint32_t sq  = smem_u32(asmem);
    const uint32_t skv = sq + 18432;           // stage s at skv + s*18432 (K), +9216 (V)

    const int tid  = threadIdx.x;
    const int wid  = tid >> 5;
    const int lane = tid & 31;
    const int g    = lane >> 2;
    const int tg   = lane & 3;

    const int b  = blockIdx.z;
    const int h  = blockIdx.y;
    const int q0 = blockIdx.x * 128;

    const int a_row = (lane & 7) + ((lane >> 3) & 1) * 8;
    const int a_k8  = ((lane >> 4) & 1) * 8;
    const int b_row = (lane & 7) + ((lane >> 4) & 1) * 8;
    const int b_k8  = ((lane >> 3) & 1) * 8;
    // V (trans) addressing
    const int v_row = (lane & 7) + ((lane >> 3) & 1) * 8;
    const int v_d8  = ((lane >> 4) & 1) * 8;

    // ---- load Q tile (128x64 fp16) ----
    #pragma unroll
    for (int i = 0; i < 4; i++) {
        int c = tid + 256 * i;
        int r = c >> 3, s_ = c & 7;
        CP_ASYNC16(sq + r * (PAD64 * 2) + s_ * 16,
                   Q + ((size_t)(b * S + q0 + r)) * D + h * DK + s_ * 8);
    }
    CP_COMMIT();

    auto issueKV = [&](int kt, int buf) {
        const uint32_t kb = skv + buf * 18432;
        #pragma unroll
        for (int i = 0; i < 2; i++) {
            int c = tid + 256 * i;
            int r = c >> 3, s_ = c & 7;
            size_t goff = ((size_t)(b * S + kt * 64 + r)) * D + h * DK + s_ * 8;
            CP_ASYNC16(kb + r * (PAD64 * 2) + s_ * 16, K + goff);
            CP_ASYNC16(kb + 9216 + r * (PAD64 * 2) + s_ * 16, V + goff);
        }
        CP_COMMIT();
    };

    issueKV(0, 0);
    issueKV(1, 1);
    asm volatile("cp.async.wait_group 1;" ::: "memory");  // Q + KV0 ready
    __syncthreads();

    // Q fragments (held all kernel): 4 k-chunks x 4 regs
    uint32_t qa[4][4];
    #pragma unroll
    for (int kc = 0; kc < 4; kc++) {
        uint32_t ad = sq + (uint32_t)(wid * 16 + a_row) * (PAD64 * 2)
                         + (uint32_t)(kc * 16 + a_k8) * 2;
        LDMATRIX_X4(qa[kc][0], qa[kc][1], qa[kc][2], qa[kc][3], ad);
    }

    float o[8][4];
    #pragma unroll
    for (int i = 0; i < 8; i++)
        #pragma unroll
        for (int e = 0; e < 4; e++) o[i][e] = 0.0f;
    float m0v = -1e30f, m1v = -1e30f, l0 = 0.0f, l1 = 0.0f;

    const float sc_log = 0.125f;   // 1/sqrt(64)

    for (int kt = 0; kt < S / 64; kt++) {
        const uint32_t kb = skv + (kt & 1) * 18432;

        // ---- QK^T: scores 16x64 per warp ----
        float sc[8][4];
        #pragma unroll
        for (int i = 0; i < 8; i++)
            #pragma unroll
            for (int e = 0; e < 4; e++) sc[i][e] = 0.0f;

        #pragma unroll
        for (int kc = 0; kc < 4; kc++) {
            uint32_t bfr[8][2];
            #pragma unroll
            for (int p = 0; p < 4; p++) {
                uint32_t bd = kb + (uint32_t)(p * 16 + b_row) * (PAD64 * 2)
                                 + (uint32_t)(kc * 16 + b_k8) * 2;
                uint32_t x0, x1, x2, x3;
                LDMATRIX_X4(x0, x1, x2, x3, bd);
                bfr[p * 2 + 0][0] = x0; bfr[p * 2 + 0][1] = x1;
                bfr[p * 2 + 1][0] = x2; bfr[p * 2 + 1][1] = x3;
            }
            #pragma unroll
            for (int nt = 0; nt < 8; nt++)
                MMA_F16(sc[nt][0], sc[nt][1], sc[nt][2], sc[nt][3],
                        qa[kc][0], qa[kc][1], qa[kc][2], qa[kc][3],
                        bfr[nt][0], bfr[nt][1]);
        }

        // ---- online softmax (scale folded into exp) ----
        float tmax0 = -1e30f, tmax1 = -1e30f;
        #pragma unroll
        for (int nt = 0; nt < 8; nt++) {
            tmax0 = fmaxf(tmax0, fmaxf(sc[nt][0], sc[nt][1]));
            tmax1 = fmaxf(tmax1, fmaxf(sc[nt][2], sc[nt][3]));
        }
        tmax0 = fmaxf(tmax0, __shfl_xor_sync(0xffffffffu, tmax0, 1));
        tmax0 = fmaxf(tmax0, __shfl_xor_sync(0xffffffffu, tmax0, 2));
        tmax1 = fmaxf(tmax1, __shfl_xor_sync(0xffffffffu, tmax1, 1));
        tmax1 = fmaxf(tmax1, __shfl_xor_sync(0xffffffffu, tmax1, 2));

        float mn0 = fmaxf(m0v, tmax0);
        float mn1 = fmaxf(m1v, tmax1);
        float corr0 = __expf(sc_log * (m0v - mn0));
        float corr1 = __expf(sc_log * (m1v - mn1));
        m0v = mn0; m1v = mn1;

        float ts0 = 0.0f, ts1 = 0.0f;
        #pragma unroll
        for (int nt = 0; nt < 8; nt++) {
            sc[nt][0] = __expf(sc_log * (sc[nt][0] - mn0));
            sc[nt][1] = __expf(sc_log * (sc[nt][1] - mn0));
            sc[nt][2] = __expf(sc_log * (sc[nt][2] - mn1));
            sc[nt][3] = __expf(sc_log * (sc[nt][3] - mn1));
            ts0 += sc[nt][0] + sc[nt][1];
            ts1 += sc[nt][2] + sc[nt][3];
        }
        ts0 += __shfl_xor_sync(0xffffffffu, ts0, 1);
        ts0 += __shfl_xor_sync(0xffffffffu, ts0, 2);
        ts1 += __shfl_xor_sync(0xffffffffu, ts1, 1);
        ts1 += __shfl_xor_sync(0xffffffffu, ts1, 2);
        l0 = l0 * corr0 + ts0;
        l1 = l1 * corr1 + ts1;

        #pragma unroll
        for (int nt = 0; nt < 8; nt++) {
            o[nt][0] *= corr0; o[nt][1] *= corr0;
            o[nt][2] *= corr1; o[nt][3] *= corr1;
        }

        // ---- PV: P (16x64 fp16 from score regs) @ V (64x64) ----
        #pragma unroll
        for (int kc = 0; kc < 4; kc++) {
            // V fragments via ldmatrix.trans: B[n=dim][k=kv]
            uint32_t vb[8][2];
            #pragma unroll
            for (int p = 0; p < 4; p++) {
                uint32_t vd = kb + 9216
                            + (uint32_t)(kc * 16 + v_row) * (PAD64 * 2)
                            + (uint32_t)(p * 16 + v_d8) * 2;
                uint32_t x0, x1, x2, x3;
                LDMATRIX_X4_T(x0, x1, x2, x3, vd);
                vb[p * 2 + 0][0] = x0; vb[p * 2 + 0][1] = x1;
                vb[p * 2 + 1][0] = x2; vb[p * 2 + 1][1] = x3;
            }
            // pack P fragment for this k-chunk from score tiles 2kc, 2kc+1
            __half2 p0 = __floats2half2_rn(sc[2 * kc][0],     sc[2 * kc][1]);
            __half2 p1 = __floats2half2_rn(sc[2 * kc][2],     sc[2 * kc][3]);
            __half2 p2 = __floats2half2_rn(sc[2 * kc + 1][0], sc[2 * kc + 1][1]);
            __half2 p3 = __floats2half2_rn(sc[2 * kc + 1][2], sc[2 * kc + 1][3]);
            uint32_t pa0 = *(uint32_t*)&p0, pa1 = *(uint32_t*)&p1;
            uint32_t pa2 = *(uint32_t*)&p2, pa3 = *(uint32_t*)&p3;

            #pragma unroll
            for (int nt = 0; nt < 8; nt++)
                MMA_F16(o[nt][0], o[nt][1], o[nt][2], o[nt][3],
                        pa0, pa1, pa2, pa3, vb[nt][0], vb[nt][1]);
        }

        __syncthreads();                     // all warps done with this buffer
        if (kt + 2 < S / 64) {
            issueKV(kt + 2, kt & 1);
            asm volatile("cp.async.wait_group 1;" ::: "memory");
        } else {
            asm volatile("cp.async.wait_group 0;" ::: "memory");
        }
        __syncthreads();
    }

    // ---- finalize ----
    const float inv0 = 1.0f / l0;
    const float inv1 = 1.0f / l1;
    const int row0 = q0 + wid * 16 + g;
    #pragma unroll
    for (int nt = 0; nt < 8; nt++) {
        const int col = h * DK + nt * 8 + tg * 2;
        *(float2*)(X + ((size_t)(b * S + row0)) * D + col) =
            make_float2(o[nt][0] * inv0, o[nt][1] * inv0);
        *(float2*)(X + ((size_t)(b * S + row0 + 8)) * D + col) =
            make_float2(o[nt][2] * inv1, o[nt][3] * inv1);
    }
}

// ----------------------------------------------------------------------------
// Launch
// ----------------------------------------------------------------------------
extern "C" void kernel_launch(void* const* d_in, const int* in_sizes, int n_in,
                              void* d_out, int out_size)
{
    const float* q  = (const float*)d_in[0];
    const float* k  = (const float*)d_in[1];
    const float* v  = (const float*)d_in[2];
    const float* Wq = (const float*)d_in[3];
    const float* bq = (const float*)d_in[4];
    const float* Wk = (const float*)d_in[5];
    const float* bk = (const float*)d_in[6];
    const float* Wv = (const float*)d_in[7];
    const float* bv = (const float*)d_in[8];
    const float* Wo = (const float*)d_in[9];
    const float* bo = (const float*)d_in[10];
    float* out = (float*)d_out;

    float *X;
    __half *Qh, *Kh, *Vh;
    __nv_bfloat16 *Abig, *Wbig;
    cudaGetSymbolAddress((void**)&Qh,   g_Qh);
    cudaGetSymbolAddress((void**)&Kh,   g_Kh);
    cudaGetSymbolAddress((void**)&Vh,   g_Vh);
    cudaGetSymbolAddress((void**)&X,    g_X);
    cudaGetSymbolAddress((void**)&Abig, g_Abig);
    cudaGetSymbolAddress((void**)&Wbig, g_Wbig);

    cudaFuncSetAttribute(gemm_mma_kernel<float>,
                         cudaFuncAttributeMaxDynamicSharedMemorySize, GEMM_SMEM);
    cudaFuncSetAttribute(gemm_mma_kernel<__half>,
                         cudaFuncAttributeMaxDynamicSharedMemorySize, GEMM_SMEM);
    cudaFuncSetAttribute(attn_mma_kernel,
                         cudaFuncAttributeMaxDynamicSharedMemorySize, AT_SMEM);

    dim3 gemmGrid(D / 128, M / 128);   // (8, 64)

    // Q/K/V projections -> fp16
    split3_w_kernel<<<D, 256>>>(Wq, Wbig);
    split3_a_kernel<<<M, 256>>>(q, Abig);
    gemm_mma_kernel<__half><<<gemmGrid, 256, GEMM_SMEM>>>(Abig, Wbig, bq, Qh, K3);

    split3_w_kernel<<<D, 256>>>(Wk, Wbig);
    split3_a_kernel<<<M, 256>>>(k, Abig);
    gemm_mma_kernel<__half><<<gemmGrid, 256, GEMM_SMEM>>>(Abig, Wbig, bk, Kh, K3);

    split3_w_kernel<<<D, 256>>>(Wv, Wbig);
    split3_a_kernel<<<M, 256>>>(v, Abig);
    gemm_mma_kernel<__half><<<gemmGrid, 256, GEMM_SMEM>>>(Abig, Wbig, bv, Vh, K3);

    // fp16 HMMA flash attention
    dim3 attnGrid(S / 128, H, B);      // (16, 16, 4)
    attn_mma_kernel<<<attnGrid, 256, AT_SMEM>>>(Qh, Kh, Vh, X);

    // Output projection (fp32 out)
    split3_w_kernel<<<D, 256>>>(Wo, Wbig);
    split3_a_kernel<<<M, 256>>>(X, Abig);
    gemm_mma_kernel<float><<<gemmGrid, 256, GEMM_SMEM>>>(Abig, Wbig, bo, out, K3);
}